// round 11
// baseline (speedup 1.0000x reference)
#include <cuda_runtime.h>
#include <cuda_fp16.h>
#include <cstdint>

// out[M,256] = X[M,256] * tril(W)^T + b  via single fp16 mma.sync.
// v9 structure (best: 146us) with X staging interleaved into k-steps so LDG
// latency is covered by MMA work. CTA 256x64, 8 warps (4x2), warp tile 64x32,
// K chunk 32, double-buffered X, W preloaded, triangular K-skip, 2 CTAs/SM.

#define TDIM 256
#define BM   256
#define BN   64
#define NTHREADS 256

// smem: W[64][512B] swizzled (reused as epilogue bounce) | X stage0 | X stage1
#define OW   0
#define OX0  32768
#define OX1  49152
#define SM_TOTAL 65536

__device__ __half g_Wh[TDIM * TDIM];

__global__ void prep_w(const float* __restrict__ W) {
    int n = blockIdx.x, k = threadIdx.x;
    float v = (k <= n) ? W[n * TDIM + k] : 0.0f;
    g_Wh[n * TDIM + k] = __float2half_rn(v);
}

__device__ __forceinline__ uint32_t smem_u32(const void* p) {
    uint32_t a;
    asm("{ .reg .u64 t; cvta.to.shared.u64 t, %1; cvt.u32.u64 %0, t; }" : "=r"(a) : "l"(p));
    return a;
}
// W layout: row n = 512B (256 fp16 K-cols), 16B chunk c swizzled by n&7
__device__ __forceinline__ uint32_t woff(int n, int c) {
    return (uint32_t)(n * 512 + ((c ^ (n & 7)) << 4));
}
// X fp16 layout: two 64B rows per 128B smem row; 16B chunkin 0..7 swizzled
__device__ __forceinline__ uint32_t xoff(int row, int chunkin) {
    return (uint32_t)((row >> 1) * 128 + ((chunkin ^ ((row >> 1) & 7)) << 4));
}
__device__ __forceinline__ uint32_t xsts(int row, int fq) {
    int chunkin = ((row & 1) << 2) | (fq >> 1);
    return xoff(row, chunkin) + (uint32_t)((fq & 1) * 8);
}

#define CP16(dst, src) \
    asm volatile("cp.async.cg.shared.global [%0], [%1], 16;" :: "r"(dst), "l"(src) : "memory")
#define CP_COMMIT() asm volatile("cp.async.commit_group;" ::: "memory")
#define CP_WAIT0()  asm volatile("cp.async.wait_group 0;" ::: "memory")

__device__ __forceinline__ void ldsm4(uint32_t (&r)[4], uint32_t a) {
    asm volatile("ldmatrix.sync.aligned.m8n8.x4.shared.b16 {%0,%1,%2,%3}, [%4];"
        : "=r"(r[0]), "=r"(r[1]), "=r"(r[2]), "=r"(r[3]) : "r"(a));
}
__device__ __forceinline__ void mma16816(float (&d)[4], const uint32_t (&a)[4],
                                         const uint32_t* b) {
    asm volatile("mma.sync.aligned.m16n8k16.row.col.f32.f16.f16.f32 "
        "{%0,%1,%2,%3}, {%4,%5,%6,%7}, {%8,%9}, {%0,%1,%2,%3};"
        : "+f"(d[0]), "+f"(d[1]), "+f"(d[2]), "+f"(d[3])
        : "r"(a[0]), "r"(a[1]), "r"(a[2]), "r"(a[3]), "r"(b[0]), "r"(b[1]));
}
__device__ __forceinline__ uint32_t pack2f(float lo, float hi) {
    uint32_t r;
    asm("cvt.rn.f16x2.f32 %0, %1, %2;" : "=r"(r) : "f"(hi), "f"(lo));
    return r;
}
__device__ __forceinline__ void xstore(char* buf, int row, int fq, float4 v) {
    uint2 h = make_uint2(pack2f(v.x, v.y), pack2f(v.z, v.w));
    *reinterpret_cast<uint2*>(buf + xsts(row, fq)) = h;
}

__global__ __launch_bounds__(NTHREADS, 2)
void triu_v11(const float* __restrict__ X, const float* __restrict__ bias,
              float* __restrict__ out)
{
    extern __shared__ char smem[];
    const uint32_t sb = smem_u32(smem);
    const int tid = threadIdx.x;
    const int wid = tid >> 5, lane = tid & 31;

    const int bid = blockIdx.x;
    const int nb = bid & 3;                           // n-block 0..3
    const size_t m0 = (size_t)(bid >> 2) * BM;
    const int n0 = nb * BN;
    const int nch = 2 * (nb + 1);                     // CK=32 chunks: 2,4,6,8

    const int rw = wid >> 1;                          // 0..3 (64 rows each)
    const int cw = wid & 1;                           // 0..1 (32 cols each)

    // X staging coords: full-row float4 loads (4 rows/warp per LDG, 4 lines/instr)
    const int srow = tid >> 3, sfq = tid & 7;

    // ---- prologue: preload needed W via cp.async ----
    const int wchunks = 8 * (nb + 1);                 // 16B chunks per row (<=32)
    #pragma unroll
    for (int i = 0; i < 8; i++) {
        int s = tid + i * NTHREADS;                   // 0..2047
        int n = s >> 5, c = s & 31;
        if (c < wchunks)
            CP16(sb + OW + woff(n, c), &g_Wh[(n0 + n) * TDIM + c * 8]);
    }
    CP_COMMIT();

    // ---- stage X chunk 0 ----
    #pragma unroll
    for (int p = 0; p < 8; p++) {
        int row = p * 32 + srow;
        float4 v = *reinterpret_cast<const float4*>(&X[(m0 + row) * TDIM + sfq * 4]);
        xstore(smem + OX0, row, sfq, v);
    }
    CP_WAIT0();
    __syncthreads();

    float acc[4][4][4];
    #pragma unroll
    for (int i = 0; i < 4; i++)
        #pragma unroll
        for (int j = 0; j < 4; j++)
            #pragma unroll
            for (int e = 0; e < 4; e++) acc[i][j][e] = 0.0f;

    const int g = lane >> 3;
    float4 xv[4];
    int st = 0;
    for (int c = 0; c < nch; c++) {
        const bool more = (c + 1 < nch);
        const int k0n = (c + 1) * 32;
        const uint32_t bs = sb + (st ? OX1 : OX0);
        char* nbuf = smem + (st ? OX0 : OX1);

        // LDG batch1 (rows 0..127 of next chunk) — covered by kstep0 below
        if (more) {
            #pragma unroll
            for (int p = 0; p < 4; p++) {
                int row = p * 32 + srow;
                xv[p] = *reinterpret_cast<const float4*>(&X[(m0 + row) * TDIM + k0n + sfq * 4]);
            }
        }

        // ---- kstep 0 ----
        {
            const int kg = c * 2;
            uint32_t ah[4][4], bh[4][2];
            #pragma unroll
            for (int i = 0; i < 4; i++) {
                int ar = rw * 64 + i * 16 + (lane & 15);
                int chunkin = ((ar & 1) << 2) | (lane >> 4);
                ldsm4(ah[i], bs + xoff(ar, chunkin));
            }
            #pragma unroll
            for (int j2 = 0; j2 < 2; j2++) {
                int br = cw * 32 + j2 * 16 + ((g >> 1) << 3) + (lane & 7);
                int wc = 2 * kg + (g & 1);
                uint32_t r[4];
                ldsm4(r, sb + OW + woff(br, wc));
                bh[2 * j2][0] = r[0]; bh[2 * j2][1] = r[1];
                bh[2 * j2 + 1][0] = r[2]; bh[2 * j2 + 1][1] = r[3];
            }
            #pragma unroll
            for (int i = 0; i < 4; i++)
                #pragma unroll
                for (int j = 0; j < 4; j++)
                    mma16816(acc[i][j], ah[i], bh[j]);
        }

        // STS batch1, then LDG batch2 (rows 128..255) — covered by kstep1
        if (more) {
            #pragma unroll
            for (int p = 0; p < 4; p++)
                xstore(nbuf, p * 32 + srow, sfq, xv[p]);
            #pragma unroll
            for (int p = 0; p < 4; p++) {
                int row = (p + 4) * 32 + srow;
                xv[p] = *reinterpret_cast<const float4*>(&X[(m0 + row) * TDIM + k0n + sfq * 4]);
            }
        }

        // ---- kstep 1 ----
        {
            const int kg = c * 2 + 1;
            uint32_t ah[4][4], bh[4][2];
            #pragma unroll
            for (int i = 0; i < 4; i++) {
                int ar = rw * 64 + i * 16 + (lane & 15);
                int chunkin = ((ar & 1) << 2) | (2 + (lane >> 4));
                ldsm4(ah[i], bs + xoff(ar, chunkin));
            }
            #pragma unroll
            for (int j2 = 0; j2 < 2; j2++) {
                int br = cw * 32 + j2 * 16 + ((g >> 1) << 3) + (lane & 7);
                int wc = 2 * kg + (g & 1);
                uint32_t r[4];
                ldsm4(r, sb + OW + woff(br, wc));
                bh[2 * j2][0] = r[0]; bh[2 * j2][1] = r[1];
                bh[2 * j2 + 1][0] = r[2]; bh[2 * j2 + 1][1] = r[3];
            }
            #pragma unroll
            for (int i = 0; i < 4; i++)
                #pragma unroll
                for (int j = 0; j < 4; j++)
                    mma16816(acc[i][j], ah[i], bh[j]);
        }

        // STS batch2, close the chunk
        if (more) {
            #pragma unroll
            for (int p = 0; p < 4; p++)
                xstore(nbuf, (p + 4) * 32 + srow, sfq, xv[p]);
        }
        __syncthreads();
        st ^= 1;
    }

    // ---- epilogue: per-warp smem bounce -> coalesced STG.128 ----
    char* wbuf = smem + wid * 4096;                   // warp-private 32x32 f32 buffer
    const int ncol0 = n0 + cw * 32 + 2 * (lane & 3);
    float2 bj[4];
    #pragma unroll
    for (int j = 0; j < 4; j++)
        bj[j] = *reinterpret_cast<const float2*>(&bias[ncol0 + j * 8]);

    const size_t growbase = m0 + rw * 64;
    const int gcol = n0 + cw * 32 + (lane & 7) * 4;
    #pragma unroll
    for (int h = 0; h < 2; h++) {
        #pragma unroll
        for (int i2 = 0; i2 < 2; i2++) {
            const int i = 2 * h + i2;
            #pragma unroll
            for (int j = 0; j < 4; j++) {
                int chunk = 2 * j + ((lane & 3) >> 1);
                int off = (lane & 1) * 8;
                int rl0 = i2 * 16 + (lane >> 2), rl1 = rl0 + 8;
                float2 v0 = make_float2(acc[i][j][0] + bj[j].x, acc[i][j][1] + bj[j].y);
                float2 v1 = make_float2(acc[i][j][2] + bj[j].x, acc[i][j][3] + bj[j].y);
                *reinterpret_cast<float2*>(wbuf + rl0 * 128 + ((chunk ^ (rl0 & 7)) << 4) + off) = v0;
                *reinterpret_cast<float2*>(wbuf + rl1 * 128 + ((chunk ^ (rl1 & 7)) << 4) + off) = v1;
            }
        }
        __syncwarp();
        #pragma unroll
        for (int it = 0; it < 8; it++) {
            int rl = it * 4 + (lane >> 3);
            int ch = (lane & 7) ^ (rl & 7);
            float4 v = *reinterpret_cast<const float4*>(wbuf + rl * 128 + (ch << 4));
            size_t grow = growbase + h * 32 + rl;
            *reinterpret_cast<float4*>(&out[grow * TDIM + gcol]) = v;
        }
        __syncwarp();
    }
}

extern "C" void kernel_launch(void* const* d_in, const int* in_sizes, int n_in,
                              void* d_out, int out_size)
{
    const float* x = (const float*)d_in[0];
    const float* W = (const float*)d_in[1];
    const float* b = (const float*)d_in[2];
    float* out = (float*)d_out;

    prep_w<<<TDIM, TDIM>>>(W);

    cudaFuncSetAttribute(triu_v11, cudaFuncAttributeMaxDynamicSharedMemorySize, SM_TOTAL);
    const int M = in_sizes[0] / TDIM;                 // 262144
    const int nblocks = (M / BM) * (TDIM / BN);       // 4096
    triu_v11<<<nblocks, NTHREADS, SM_TOTAL>>>(x, b, out);
}

// round 12
// speedup vs baseline: 1.2307x; 1.2307x over previous
#include <cuda_runtime.h>
#include <cuda_fp16.h>
#include <cstdint>

// out[M,256] = X[M,256] * tril(W)^T + b  via single fp16 mma.sync.
// v9 access patterns (full-row LDG.128 staging, smem-bounce STG.128 epilogue)
// in a 128x64 / 4-warp geometry -> 4 CTAs/SM (4 independent barrier domains).
// Warp tile 64x32, K chunk 32, double-buffered X, W preloaded, triangular skip.

#define TDIM 256
#define BM   128
#define BN   64
#define NTHREADS 128

// smem: W[64][512B] swizzled (reused as epilogue bounce) | X stage0 | X stage1
#define OW   0
#define OX0  32768
#define OX1  40960
#define SM_TOTAL 49152

__device__ __half g_Wh[TDIM * TDIM];

__global__ void prep_w(const float* __restrict__ W) {
    int n = blockIdx.x, k = threadIdx.x;
    float v = (k <= n) ? W[n * TDIM + k] : 0.0f;
    g_Wh[n * TDIM + k] = __float2half_rn(v);
}

__device__ __forceinline__ uint32_t smem_u32(const void* p) {
    uint32_t a;
    asm("{ .reg .u64 t; cvta.to.shared.u64 t, %1; cvt.u32.u64 %0, t; }" : "=r"(a) : "l"(p));
    return a;
}
// W layout: row n = 512B (256 fp16 K-cols), 16B chunk c swizzled by n&7
__device__ __forceinline__ uint32_t woff(int n, int c) {
    return (uint32_t)(n * 512 + ((c ^ (n & 7)) << 4));
}
// X fp16 layout: two 64B rows per 128B smem row; 16B chunkin 0..7 swizzled
__device__ __forceinline__ uint32_t xoff(int row, int chunkin) {
    return (uint32_t)((row >> 1) * 128 + ((chunkin ^ ((row >> 1) & 7)) << 4));
}
__device__ __forceinline__ uint32_t xsts(int row, int fq) {
    int chunkin = ((row & 1) << 2) | (fq >> 1);
    return xoff(row, chunkin) + (uint32_t)((fq & 1) * 8);
}

#define CP16(dst, src) \
    asm volatile("cp.async.cg.shared.global [%0], [%1], 16;" :: "r"(dst), "l"(src) : "memory")
#define CP_COMMIT() asm volatile("cp.async.commit_group;" ::: "memory")
#define CP_WAIT0()  asm volatile("cp.async.wait_group 0;" ::: "memory")

__device__ __forceinline__ void ldsm4(uint32_t (&r)[4], uint32_t a) {
    asm volatile("ldmatrix.sync.aligned.m8n8.x4.shared.b16 {%0,%1,%2,%3}, [%4];"
        : "=r"(r[0]), "=r"(r[1]), "=r"(r[2]), "=r"(r[3]) : "r"(a));
}
__device__ __forceinline__ void mma16816(float (&d)[4], const uint32_t (&a)[4],
                                         const uint32_t* b) {
    asm volatile("mma.sync.aligned.m16n8k16.row.col.f32.f16.f16.f32 "
        "{%0,%1,%2,%3}, {%4,%5,%6,%7}, {%8,%9}, {%0,%1,%2,%3};"
        : "+f"(d[0]), "+f"(d[1]), "+f"(d[2]), "+f"(d[3])
        : "r"(a[0]), "r"(a[1]), "r"(a[2]), "r"(a[3]), "r"(b[0]), "r"(b[1]));
}
__device__ __forceinline__ uint32_t pack2f(float lo, float hi) {
    uint32_t r;
    asm("cvt.rn.f16x2.f32 %0, %1, %2;" : "=r"(r) : "f"(hi), "f"(lo));
    return r;
}
__device__ __forceinline__ void xstore(char* buf, int row, int fq, float4 v) {
    uint2 h = make_uint2(pack2f(v.x, v.y), pack2f(v.z, v.w));
    *reinterpret_cast<uint2*>(buf + xsts(row, fq)) = h;
}

__global__ __launch_bounds__(NTHREADS, 4)
void triu_v12(const float* __restrict__ X, const float* __restrict__ bias,
              float* __restrict__ out)
{
    extern __shared__ char smem[];
    const uint32_t sb = smem_u32(smem);
    const int tid = threadIdx.x;
    const int wid = tid >> 5, lane = tid & 31;

    const int bid = blockIdx.x;
    const int nb = bid & 3;                           // n-block 0..3
    const size_t m0 = (size_t)(bid >> 2) * BM;
    const int n0 = nb * BN;
    const int nch = 2 * (nb + 1);                     // CK=32 chunks: 2,4,6,8

    const int rw = wid >> 1;                          // 0..1 (64 rows each)
    const int cw = wid & 1;                           // 0..1 (32 cols each)

    // X staging coords: full-row float4 loads (4 rows/warp per LDG, 4 lines/instr)
    const int srow = tid >> 3, sfq = tid & 7;         // rows 0..15 per pass

    // ---- prologue: preload needed W via cp.async ----
    const int wchunks = 8 * (nb + 1);                 // 16B chunks per row (<=32)
    #pragma unroll
    for (int i = 0; i < 16; i++) {
        int s = tid + i * NTHREADS;                   // 0..2047
        int n = s >> 5, c = s & 31;
        if (c < wchunks)
            CP16(sb + OW + woff(n, c), &g_Wh[(n0 + n) * TDIM + c * 8]);
    }
    CP_COMMIT();

    // ---- stage X chunk 0 (128 rows x 32 cols) ----
    #pragma unroll
    for (int p = 0; p < 8; p++) {
        int row = p * 16 + srow;
        float4 v = *reinterpret_cast<const float4*>(&X[(m0 + row) * TDIM + sfq * 4]);
        xstore(smem + OX0, row, sfq, v);
    }
    CP_WAIT0();
    __syncthreads();

    float acc[4][4][4];
    #pragma unroll
    for (int i = 0; i < 4; i++)
        #pragma unroll
        for (int j = 0; j < 4; j++)
            #pragma unroll
            for (int e = 0; e < 4; e++) acc[i][j][e] = 0.0f;

    const int g = lane >> 3;
    float4 xv[4];                                     // prefetch: passes 0..3
    int st = 0;
    for (int c = 0; c < nch; c++) {
        const bool more = (c + 1 < nch);
        const int k0n = (c + 1) * 32;
        if (more) {
            #pragma unroll
            for (int p = 0; p < 4; p++) {
                int row = p * 16 + srow;
                xv[p] = *reinterpret_cast<const float4*>(&X[(m0 + row) * TDIM + k0n + sfq * 4]);
            }
        }

        const uint32_t bs = sb + (st ? OX1 : OX0);
        #pragma unroll
        for (int kk = 0; kk < 2; kk++) {
            const int kg = c * 2 + kk;                // global k16 index
            uint32_t ah[4][4], bh[4][2];
            #pragma unroll
            for (int i = 0; i < 4; i++) {
                int ar = rw * 64 + i * 16 + (lane & 15);
                int chunkin = ((ar & 1) << 2) | (2 * kk + (lane >> 4));
                ldsm4(ah[i], bs + xoff(ar, chunkin));
            }
            #pragma unroll
            for (int j2 = 0; j2 < 2; j2++) {
                int br = cw * 32 + j2 * 16 + ((g >> 1) << 3) + (lane & 7);
                int wc = 2 * kg + (g & 1);
                uint32_t r[4];
                ldsm4(r, sb + OW + woff(br, wc));
                bh[2 * j2][0] = r[0]; bh[2 * j2][1] = r[1];
                bh[2 * j2 + 1][0] = r[2]; bh[2 * j2 + 1][1] = r[3];
            }
            #pragma unroll
            for (int i = 0; i < 4; i++)
                #pragma unroll
                for (int j = 0; j < 4; j++)
                    mma16816(acc[i][j], ah[i], bh[j]);
        }

        if (more) {
            char* nbuf = smem + (st ? OX0 : OX1);
            #pragma unroll
            for (int p = 0; p < 4; p++)               // prefetched passes
                xstore(nbuf, p * 16 + srow, sfq, xv[p]);
            #pragma unroll
            for (int p = 4; p < 8; p++) {             // late passes
                int row = p * 16 + srow;
                float4 v = *reinterpret_cast<const float4*>(&X[(m0 + row) * TDIM + k0n + sfq * 4]);
                xstore(nbuf, row, sfq, v);
            }
        }
        __syncthreads();
        st ^= 1;
    }
    // loop-final __syncthreads: all W/X smem reads done -> safe to reuse OW region

    // ---- epilogue: per-warp smem bounce -> coalesced STG.128 ----
    char* wbuf = smem + wid * 4096;                   // warp-private 32x32 f32 buffer
    const int ncol0 = n0 + cw * 32 + 2 * (lane & 3);
    float2 bj[4];
    #pragma unroll
    for (int j = 0; j < 4; j++)
        bj[j] = *reinterpret_cast<const float2*>(&bias[ncol0 + j * 8]);

    const size_t growbase = m0 + rw * 64;
    const int gcol = n0 + cw * 32 + (lane & 7) * 4;
    #pragma unroll
    for (int h = 0; h < 2; h++) {
        #pragma unroll
        for (int i2 = 0; i2 < 2; i2++) {
            const int i = 2 * h + i2;
            #pragma unroll
            for (int j = 0; j < 4; j++) {
                int chunk = 2 * j + ((lane & 3) >> 1);
                int off = (lane & 1) * 8;
                int rl0 = i2 * 16 + (lane >> 2), rl1 = rl0 + 8;
                float2 v0 = make_float2(acc[i][j][0] + bj[j].x, acc[i][j][1] + bj[j].y);
                float2 v1 = make_float2(acc[i][j][2] + bj[j].x, acc[i][j][3] + bj[j].y);
                *reinterpret_cast<float2*>(wbuf + rl0 * 128 + ((chunk ^ (rl0 & 7)) << 4) + off) = v0;
                *reinterpret_cast<float2*>(wbuf + rl1 * 128 + ((chunk ^ (rl1 & 7)) << 4) + off) = v1;
            }
        }
        __syncwarp();
        #pragma unroll
        for (int it = 0; it < 8; it++) {
            int rl = it * 4 + (lane >> 3);
            int ch = (lane & 7) ^ (rl & 7);
            float4 v = *reinterpret_cast<const float4*>(wbuf + rl * 128 + (ch << 4));
            size_t grow = growbase + h * 32 + rl;
            *reinterpret_cast<float4*>(&out[grow * TDIM + gcol]) = v;
        }
        __syncwarp();
    }
}

extern "C" void kernel_launch(void* const* d_in, const int* in_sizes, int n_in,
                              void* d_out, int out_size)
{
    const float* x = (const float*)d_in[0];
    const float* W = (const float*)d_in[1];
    const float* b = (const float*)d_in[2];
    float* out = (float*)d_out;

    prep_w<<<TDIM, TDIM>>>(W);

    cudaFuncSetAttribute(triu_v12, cudaFuncAttributeMaxDynamicSharedMemorySize, SM_TOTAL);
    const int M = in_sizes[0] / TDIM;                 // 262144
    const int nblocks = (M / BM) * (TDIM / BN);       // 8192
    triu_v12<<<nblocks, NTHREADS, SM_TOTAL>>>(x, b, out);
}